// round 3
// baseline (speedup 1.0000x reference)
#include <cuda_runtime.h>
#include <cuda_bf16.h>
#include <math_constants.h>

// Logcumsumexp along axis 1 of x[8, 4096, 1024] (f32).
// (m, s) domain scan: u = x*log2e, m = running max(u), s = sum 2^(u_j - m),
// y = (m + log2(s)) * ln2.
// One CTA = 32 columns x full 4096-row chain, 16 segments of 256 rows
// (one warp per segment -> every global access is a coalesced 128B line).
// Pass1: per-segment (m,s). SMEM exclusive scan stitches segments.
// Pass2: re-read x (L2-leaning), resume from prefix, emit y.

#define BATCH   8
#define LEN     4096
#define CHAN    1024
#define TILE_C  32
#define SEGS    16
#define SEGLEN  (LEN / SEGS)          // 256
#define NTHREADS (TILE_C * SEGS)      // 512

__device__ __forceinline__ float ex2f_(float x) {
    float r; asm("ex2.approx.ftz.f32 %0, %1;" : "=f"(r) : "f"(x)); return r;
}
__device__ __forceinline__ float lg2f_(float x) {
    float r; asm("lg2.approx.ftz.f32 %0, %1;" : "=f"(r) : "f"(x)); return r;
}

// Branchless combine step: given running (m, s) and new element u,
// update to (m', s') for the chain extended by u. One EX2, one FMA, two SELs.
__device__ __forceinline__ void lcse_step(float& m, float& s, float u) {
    float d = u - m;
    float e = ex2f_(-fabsf(d));       // 2^(-|u-m|), serves both cases
    bool up = d > 0.0f;               // new max
    float a = up ? e : 1.0f;          // scale on old s
    float b = up ? 1.0f : e;          // new element's contribution
    s = fmaf(s, a, b);
    m = up ? u : m;
}

// Combine two (m, s) summaries: left-prefix (M, S) absorbed with segment (mk, sk).
__device__ __forceinline__ void lcse_merge(float& M, float& S, float mk, float sk) {
    float d = mk - M;
    float e = ex2f_(-fabsf(d));
    bool up = d > 0.0f;
    float a = up ? e : 1.0f;          // scale on prefix S
    float c = up ? sk : sk * e;       // segment contribution
    S = fmaf(S, a, c);
    M = up ? mk : M;
}

__global__ __launch_bounds__(NTHREADS, 2)
void lcse_kernel(const float* __restrict__ x, float* __restrict__ out) {
    __shared__ float sm_m[SEGS][TILE_C];
    __shared__ float sm_s[SEGS][TILE_C];

    const int c   = threadIdx.x & (TILE_C - 1);   // lane = column within tile
    const int seg = threadIdx.x / TILE_C;         // warp  = segment
    const int b   = blockIdx.x / (CHAN / TILE_C);
    const int cg  = blockIdx.x % (CHAN / TILE_C);

    const int base = b * (LEN * CHAN) + cg * TILE_C + c;
    const float* xp = x   + base + seg * SEGLEN * CHAN;
    float*       op = out + base + seg * SEGLEN * CHAN;

    const float LOG2E = 1.4426950408889634f;
    const float LN2   = 0.6931471805599453f;

    // ---------------- Pass 1: per-segment (m, s) totals ----------------
    float m = -CUDART_INF_F;
    float s = 0.0f;
    #pragma unroll 8
    for (int i = 0; i < SEGLEN; i++) {
        float u = __ldg(xp + i * CHAN) * LOG2E;
        lcse_step(m, s, u);
    }
    sm_m[seg][c] = m;
    sm_s[seg][c] = s;
    __syncthreads();

    // ------- Exclusive scan over segments (warp 0; lanes = columns) -------
    if (threadIdx.x < TILE_C) {
        float M = -CUDART_INF_F;
        float S = 0.0f;
        #pragma unroll
        for (int k = 0; k < SEGS; k++) {
            float mk = sm_m[k][c];
            float sk = sm_s[k][c];
            sm_m[k][c] = M;           // write EXCLUSIVE prefix back
            sm_s[k][c] = S;
            lcse_merge(M, S, mk, sk);
        }
    }
    __syncthreads();

    // ---------------- Pass 2: rescan with prefix, emit outputs ----------------
    m = sm_m[seg][c];
    s = sm_s[seg][c];
    #pragma unroll 8
    for (int i = 0; i < SEGLEN; i++) {
        float u = __ldcs(xp + i * CHAN) * LOG2E;  // last use of x: evict-first
        lcse_step(m, s, u);
        float y = (m + lg2f_(s)) * LN2;
        __stcs(op + i * CHAN, y);                 // streaming store: keep L2 for x
    }
}

extern "C" void kernel_launch(void* const* d_in, const int* in_sizes, int n_in,
                              void* d_out, int out_size) {
    const float* x = (const float*)d_in[0];
    float* out = (float*)d_out;
    dim3 grid(BATCH * (CHAN / TILE_C));   // 256 CTAs
    dim3 block(NTHREADS);                 // 512 threads
    lcse_kernel<<<grid, block>>>(x, out);
}

// round 4
// speedup vs baseline: 1.5536x; 1.5536x over previous
#include <cuda_runtime.h>
#include <cuda_bf16.h>
#include <math_constants.h>

// Logcumsumexp along axis 1 of x[8, 4096, 1024] (f32).
// (m, s) domain scan: u = x*log2e, m = running max(u), s = sum 2^(u_j - m),
// y = (m + log2(s)) * ln2.
// One CTA = 32 columns x full 4096-row chain, 32 segments of 128 rows
// (one warp per segment -> every global access is a coalesced 128B line).
// Pass1: per-segment (m,s). SMEM exclusive scan stitches segments.
// Pass2: re-read x (L2-leaning), resume from prefix, emit y.
// R3 change: SEGS 16->32 (serial depth per thread 512->256 steps),
// 1024 thr/CTA, launch_bounds(1024,2) -> 64 warps/SM at 32 regs.

#define BATCH   8
#define LEN     4096
#define CHAN    1024
#define TILE_C  32
#define SEGS    32
#define SEGLEN  (LEN / SEGS)          // 128
#define NTHREADS (TILE_C * SEGS)      // 1024

__device__ __forceinline__ float ex2f_(float x) {
    float r; asm("ex2.approx.ftz.f32 %0, %1;" : "=f"(r) : "f"(x)); return r;
}
__device__ __forceinline__ float lg2f_(float x) {
    float r; asm("lg2.approx.ftz.f32 %0, %1;" : "=f"(r) : "f"(x)); return r;
}

// Branchless combine step: extend running (m, s) by new element u.
// One EX2, one FMA, two SELs; s-recurrence is a single FFMA chain.
__device__ __forceinline__ void lcse_step(float& m, float& s, float u) {
    float d = u - m;
    float e = ex2f_(-fabsf(d));       // 2^(-|u-m|), serves both cases
    bool up = d > 0.0f;               // new max
    float a = up ? e : 1.0f;          // scale on old s
    float b = up ? 1.0f : e;          // new element's contribution
    s = fmaf(s, a, b);
    m = up ? u : m;
}

// Absorb segment summary (mk, sk) into running prefix (M, S).
__device__ __forceinline__ void lcse_merge(float& M, float& S, float mk, float sk) {
    float d = mk - M;
    float e = ex2f_(-fabsf(d));
    bool up = d > 0.0f;
    float a = up ? e : 1.0f;
    float c = up ? sk : sk * e;
    S = fmaf(S, a, c);
    M = up ? mk : M;
}

__global__ __launch_bounds__(NTHREADS, 2)
void lcse_kernel(const float* __restrict__ x, float* __restrict__ out) {
    __shared__ float sm_m[SEGS][TILE_C];
    __shared__ float sm_s[SEGS][TILE_C];

    const int c   = threadIdx.x & (TILE_C - 1);   // lane = column within tile
    const int seg = threadIdx.x / TILE_C;         // warp  = segment
    const int b   = blockIdx.x / (CHAN / TILE_C);
    const int cg  = blockIdx.x % (CHAN / TILE_C);

    const int base = b * (LEN * CHAN) + cg * TILE_C + c;
    const float* xp = x   + base + seg * SEGLEN * CHAN;
    float*       op = out + base + seg * SEGLEN * CHAN;

    const float LOG2E = 1.4426950408889634f;
    const float LN2   = 0.6931471805599453f;

    // ---------------- Pass 1: per-segment (m, s) totals ----------------
    float m = -CUDART_INF_F;
    float s = 0.0f;
    #pragma unroll 8
    for (int i = 0; i < SEGLEN; i++) {
        float u = __ldg(xp + i * CHAN) * LOG2E;
        lcse_step(m, s, u);
    }
    sm_m[seg][c] = m;
    sm_s[seg][c] = s;
    __syncthreads();

    // ------- Exclusive scan over segments (warp 0; lanes = columns) -------
    if (threadIdx.x < TILE_C) {
        float M = -CUDART_INF_F;
        float S = 0.0f;
        #pragma unroll
        for (int k = 0; k < SEGS; k++) {
            float mk = sm_m[k][c];
            float sk = sm_s[k][c];
            sm_m[k][c] = M;           // write EXCLUSIVE prefix back
            sm_s[k][c] = S;
            lcse_merge(M, S, mk, sk);
        }
    }
    __syncthreads();

    // ---------------- Pass 2: rescan with prefix, emit outputs ----------------
    m = sm_m[seg][c];
    s = sm_s[seg][c];
    #pragma unroll 8
    for (int i = 0; i < SEGLEN; i++) {
        float u = __ldcs(xp + i * CHAN) * LOG2E;  // last use of x: evict-first
        lcse_step(m, s, u);
        float y = (m + lg2f_(s)) * LN2;
        __stcs(op + i * CHAN, y);                 // streaming store: keep L2 for x
    }
}

extern "C" void kernel_launch(void* const* d_in, const int* in_sizes, int n_in,
                              void* d_out, int out_size) {
    const float* x = (const float*)d_in[0];
    float* out = (float*)d_out;
    dim3 grid(BATCH * (CHAN / TILE_C));   // 256 CTAs
    dim3 block(NTHREADS);                 // 1024 threads
    lcse_kernel<<<grid, block>>>(x, out);
}

// round 6
// speedup vs baseline: 2.0866x; 1.3431x over previous
#include <cuda_runtime.h>
#include <cuda_bf16.h>
#include <math_constants.h>

// Logcumsumexp along axis 1 of x[8, 4096, 1024] (f32).
// (m, s) domain scan: u = x*log2e, m = running max(u), s = sum 2^(u_j - m),
// y = (m + log2(s)) * ln2.
// One CTA = 32 columns x full 4096-row chain, 32 segments of 128 rows.
// Pass1: per-segment (m,s). SMEM exclusive scan stitches segments.
// Pass2: re-read x (L2-leaning), resume from prefix, emit y.
// R4/R5: manual software pipelining — register double-buffer so batch i+1's
// 8 loads are in flight while batch i's dependent scan steps execute.

#define BATCH   8
#define LEN     4096
#define CHAN    1024
#define TILE_C  32
#define SEGS    32
#define SEGLEN  (LEN / SEGS)          // 128
#define NTHREADS (TILE_C * SEGS)      // 1024
#define UN      8                      // pipeline batch size

__device__ __forceinline__ float ex2f_(float x) {
    float r; asm("ex2.approx.ftz.f32 %0, %1;" : "=f"(r) : "f"(x)); return r;
}
__device__ __forceinline__ float lg2f_(float x) {
    float r; asm("lg2.approx.ftz.f32 %0, %1;" : "=f"(r) : "f"(x)); return r;
}

// Branchless combine step: extend running (m, s) by new element u.
__device__ __forceinline__ void lcse_step(float& m, float& s, float u) {
    float d = u - m;
    float e = ex2f_(-fabsf(d));       // 2^(-|u-m|), serves both cases
    bool up = d > 0.0f;               // new max
    float a = up ? e : 1.0f;          // scale on old s
    float b = up ? 1.0f : e;          // new element's contribution
    s = fmaf(s, a, b);
    m = up ? u : m;
}

// Absorb segment summary (mk, sk) into running prefix (M, S).
__device__ __forceinline__ void lcse_merge(float& M, float& S, float mk, float sk) {
    float d = mk - M;
    float e = ex2f_(-fabsf(d));
    bool up = d > 0.0f;
    float a = up ? e : 1.0f;
    float c = up ? sk : sk * e;
    S = fmaf(S, a, c);
    M = up ? mk : M;
}

__global__ __launch_bounds__(NTHREADS, 2)
void lcse_kernel(const float* __restrict__ x, float* __restrict__ out) {
    __shared__ float sm_m[SEGS][TILE_C];
    __shared__ float sm_s[SEGS][TILE_C];

    const int c   = threadIdx.x & (TILE_C - 1);   // lane = column within tile
    const int seg = threadIdx.x / TILE_C;         // warp  = segment
    const int b   = blockIdx.x / (CHAN / TILE_C);
    const int cg  = blockIdx.x % (CHAN / TILE_C);

    const int base = b * (LEN * CHAN) + cg * TILE_C + c;
    const float* xp = x   + base + seg * SEGLEN * CHAN;
    float*       op = out + base + seg * SEGLEN * CHAN;

    const float LOG2E = 1.4426950408889634f;
    const float LN2   = 0.6931471805599453f;

    // ---------------- Pass 1: per-segment (m, s) totals ----------------
    float m = -CUDART_INF_F;
    float s = 0.0f;
    {
        float cur[UN];
        #pragma unroll
        for (int j = 0; j < UN; j++) cur[j] = __ldg(xp + j * CHAN);

        for (int i = 0; i < SEGLEN - UN; i += UN) {
            float nxt[UN];
            #pragma unroll
            for (int j = 0; j < UN; j++) nxt[j] = __ldg(xp + (i + UN + j) * CHAN);
            #pragma unroll
            for (int j = 0; j < UN; j++) lcse_step(m, s, cur[j] * LOG2E);
            #pragma unroll
            for (int j = 0; j < UN; j++) cur[j] = nxt[j];
        }
        #pragma unroll
        for (int j = 0; j < UN; j++) lcse_step(m, s, cur[j] * LOG2E);
    }
    sm_m[seg][c] = m;
    sm_s[seg][c] = s;
    __syncthreads();

    // ------- Exclusive scan over segments (warp 0; lanes = columns) -------
    if (threadIdx.x < TILE_C) {
        float M = -CUDART_INF_F;
        float S = 0.0f;
        #pragma unroll
        for (int k = 0; k < SEGS; k++) {
            float mk = sm_m[k][c];
            float sk = sm_s[k][c];
            sm_m[k][c] = M;           // write EXCLUSIVE prefix back
            sm_s[k][c] = S;
            lcse_merge(M, S, mk, sk);
        }
    }
    __syncthreads();

    // ---------------- Pass 2: rescan with prefix, emit outputs ----------------
    m = sm_m[seg][c];
    s = sm_s[seg][c];
    {
        float cur[UN];
        #pragma unroll
        for (int j = 0; j < UN; j++) cur[j] = __ldcs(xp + j * CHAN);

        for (int i = 0; i < SEGLEN - UN; i += UN) {
            float nxt[UN];
            #pragma unroll
            for (int j = 0; j < UN; j++) nxt[j] = __ldcs(xp + (i + UN + j) * CHAN);
            #pragma unroll
            for (int j = 0; j < UN; j++) {
                lcse_step(m, s, cur[j] * LOG2E);
                float y = (m + lg2f_(s)) * LN2;
                __stcs(op + (i + j) * CHAN, y);   // streaming store: keep L2 for x
            }
            #pragma unroll
            for (int j = 0; j < UN; j++) cur[j] = nxt[j];
        }
        const int i0 = SEGLEN - UN;
        #pragma unroll
        for (int j = 0; j < UN; j++) {
            lcse_step(m, s, cur[j] * LOG2E);
            float y = (m + lg2f_(s)) * LN2;
            __stcs(op + (i0 + j) * CHAN, y);
        }
    }
}

extern "C" void kernel_launch(void* const* d_in, const int* in_sizes, int n_in,
                              void* d_out, int out_size) {
    const float* x = (const float*)d_in[0];
    float* out = (float*)d_out;
    dim3 grid(BATCH * (CHAN / TILE_C));   // 256 CTAs
    dim3 block(NTHREADS);                 // 1024 threads
    lcse_kernel<<<grid, block>>>(x, out);
}